// round 9
// baseline (speedup 1.0000x reference)
#include <cuda_runtime.h>
#include <cstdio>
#include <math.h>

// Canonical dims (confirmed via R5 diagnostic dump)
#define BLn  2048      // B*L
#define Ln   1024
#define Dn   256
#define Pn   32
#define CH   32        // chunk length (in l)
#define NCH  (BLn/CH)  // 64 chunks
#define CPB  (Ln/CH)   // 32 chunks per batch

#define MEMR ((long long)BLn * Pn * Dn)   // 16,777,216 f32 (real(memory))
#define PHN  ((long long)BLn * Pn)        // 65,536

// Scratch (__device__ globals; no allocation)
__device__ float g_values[BLn * Dn];      // 2 MB
__device__ float g_cos[BLn * Pn];         // 256 KB
__device__ float g_T[NCH * Pn * Dn];      // 2 MB  chunk totals (real)
__device__ float g_Tpre[NCH * Pn * Dn];   // 2 MB  exclusive chunk prefixes

// ---------------------------------------------------------------------------
// K1p: phase = tanh(x@Wp + bp)*pi ; cos(phase)
// One block per row; 256 threads = 8 k-groups x 32 p; smem tree reduce.
// ---------------------------------------------------------------------------
__global__ void __launch_bounds__(256) k1p_phase(
    const float* __restrict__ x,
    const float* __restrict__ Wp,   // [D, P]
    const float* __restrict__ bp,   // [P]
    float* __restrict__ out_phases,      // may be null
    float* __restrict__ out_phasors_re)  // may be null
{
    __shared__ float xr[Dn];
    __shared__ float part[8][Pn];
    const int row = blockIdx.x;
    const int tid = threadIdx.x;

    xr[tid] = x[(size_t)row * Dn + tid];
    __syncthreads();

    const int p = tid & 31, g = tid >> 5;
    const int k0 = g * 32;
    float s = 0.0f;
#pragma unroll
    for (int k = 0; k < 32; ++k)
        s = fmaf(xr[k0 + k], Wp[(k0 + k) * Pn + p], s);
    part[g][p] = s;
    __syncthreads();

    if (tid < Pn) {
        float pacc = bp[tid];
#pragma unroll
        for (int gg = 0; gg < 8; ++gg) pacc += part[gg][tid];
        const float phase = tanhf(pacc) * 3.14159274101257324f;
        const float c = cosf(phase);
        const size_t idx = (size_t)row * Pn + tid;
        g_cos[idx] = c;
        if (out_phases)     out_phases[idx]     = phase;
        if (out_phasors_re) out_phasors_re[idx] = c;
    }
}

// ---------------------------------------------------------------------------
// K1v: values = x@Wv + bv
// 8 rows/block -> 256 blocks; block dim3(64,4); thread = 2 rows x 4 cols.
// ---------------------------------------------------------------------------
__global__ void __launch_bounds__(256) k1v_values(
    const float* __restrict__ x,
    const float* __restrict__ Wv,   // [D, D]
    const float* __restrict__ bv)   // [D]
{
    __shared__ float xs[8][Dn];     // 8 KB
    const int tx  = threadIdx.x;    // 0..63 -> float4 col group
    const int ty  = threadIdx.y;    // 0..3
    const int tid = ty * 64 + tx;
    const int row0 = blockIdx.x * 8;

    for (int i = tid; i < 8 * Dn; i += 256)
        xs[i >> 8][i & (Dn - 1)] = x[(size_t)row0 * Dn + i];
    __syncthreads();

    const float4 bvv = reinterpret_cast<const float4*>(bv)[tx];
    float4 a0 = bvv, a1 = bvv;

    const float4* Wv4 = reinterpret_cast<const float4*>(Wv);
#pragma unroll 8
    for (int k = 0; k < Dn; ++k) {
        const float4 w  = Wv4[k * 64 + tx];
        const float  x0 = xs[ty][k];
        const float  x1 = xs[ty + 4][k];
        a0.x = fmaf(x0, w.x, a0.x);
        a0.y = fmaf(x0, w.y, a0.y);
        a0.z = fmaf(x0, w.z, a0.z);
        a0.w = fmaf(x0, w.w, a0.w);
        a1.x = fmaf(x1, w.x, a1.x);
        a1.y = fmaf(x1, w.y, a1.y);
        a1.z = fmaf(x1, w.z, a1.z);
        a1.w = fmaf(x1, w.w, a1.w);
    }
    reinterpret_cast<float4*>(g_values)[(size_t)(row0 + ty) * 64 + tx]     = a0;
    reinterpret_cast<float4*>(g_values)[(size_t)(row0 + ty + 4) * 64 + tx] = a1;
}

// ---------------------------------------------------------------------------
// K2: chunk totals T[ch][p][d] = sum_{l in ch} cos[l][p] * value[l][d]
// grid = NCH*4 (d-quarters) = 256 blocks; 256 threads = 64 d x 4 p-groups.
// Each thread: 8 p-accumulators over 32 l.
// ---------------------------------------------------------------------------
__global__ void __launch_bounds__(256) k2_chunktotals()
{
    __shared__ float cs[CH][Pn];   // 4 KB
    const int ch = blockIdx.x >> 2;
    const int dq = blockIdx.x & 3;
    const int lb = ch * CH;
    const int t  = threadIdx.x;
    const int d  = dq * 64 + (t & 63);
    const int p0 = (t >> 6) * 8;

    for (int i = t; i < CH * Pn; i += 256)
        cs[i >> 5][i & 31] = g_cos[(size_t)lb * Pn + i];
    __syncthreads();

    float acc[8];
#pragma unroll
    for (int i = 0; i < 8; ++i) acc[i] = 0.0f;

#pragma unroll 4
    for (int l = 0; l < CH; ++l) {
        const float v = g_values[(size_t)(lb + l) * Dn + d];
#pragma unroll
        for (int i = 0; i < 8; ++i)
            acc[i] = fmaf(cs[l][p0 + i], v, acc[i]);
    }
#pragma unroll
    for (int i = 0; i < 8; ++i)
        g_T[((size_t)ch * Pn + p0 + i) * Dn + d] = acc[i];
}

// ---------------------------------------------------------------------------
// K2b: exclusive prefix over the 32 chunks of each batch.
// grid = 2 batches * 32 p * 4 dq = 256 blocks, 64 threads (float4 of d).
// All 32 loads issued up front (high MLP), prefix in regs, 32 stores.
// ---------------------------------------------------------------------------
__global__ void __launch_bounds__(64) k2b_prefix()
{
    const int dq    = blockIdx.x & 3;
    const int p     = (blockIdx.x >> 2) & 31;
    const int batch = blockIdx.x >> 7;
    const int ch0   = batch * CPB;
    const int t     = threadIdx.x;          // 0..63
    const int d4    = dq * 64 + t;          // float4 index into Dn/4=64... (see below)

    // float4 granularity: Dn/4 = 64 groups; dq selects 16-group quarter
    const int g4 = dq * 16 + (t & 15);      // 0..63 float4 groups
    const int pp = p;                        // alias
    (void)d4;

    // Use 64 threads as 4 sub-lanes x 16 groups? Simpler: 64 threads cover
    // 64 float4 groups when dq==0..3 handle p-pairs instead. Reindex:
    // block covers (batch, p, dq) with dq in 0..3 BUT threads cover all 64
    // float4 groups and dq splits p into sub-iterations? Keep it simple:
    // each block handles one (batch, p, dq); threads 0..15 cover the 16
    // float4 groups of this quarter; threads 16..63 idle would waste 75%.
    // Instead: threads 0..63 cover 64 float4 groups, and dq selects which
    // 8 chunks of the 32 to OWN? No — prefix is serial in chunks.
    //
    // Final layout: ignore dq for data split; blocks with dq>0 handle
    // p+32*? -> invalid. So: collapse — only use 2*32 = 64 (batch,p) combos,
    // 4 blocks each redundant? No. Use dq to split the 64 float4 groups:
    // threads cover 16 groups (t>>2 gives 16 groups, t&3 unused?) — wasteful.
    //
    // Clean solution: 64 threads each own ONE float4 group (64 groups = Dn/4),
    // grid = 2*32 (batch,p) * 1 = 64 blocks... but that was the slow config's
    // parallelism. The fix is MLP, not blocks: 32 front-batched LDG.128 per
    // thread hides latency even at 64 blocks. dq blocks beyond 0 exit.
    if (dq != 0) return;

    const float4* T4   = reinterpret_cast<const float4*>(g_T);
    float4*       Tp4  = reinterpret_cast<float4*>(g_Tpre);
    const size_t  base = ((size_t)ch0 * Pn + pp) * (Dn / 4) + (t & 63);
    const size_t  str  = (size_t)Pn * (Dn / 4);
    (void)g4;

    float4 v[CPB];
#pragma unroll
    for (int c = 0; c < CPB; ++c)
        v[c] = T4[base + (size_t)c * str];

    float4 run = make_float4(0.f, 0.f, 0.f, 0.f);
#pragma unroll
    for (int c = 0; c < CPB; ++c) {
        const float4 cur = v[c];
        Tp4[base + (size_t)c * str] = run;
        run.x += cur.x;
        run.y += cur.y;
        run.z += cur.z;
        run.w += cur.w;
    }
}

// ---------------------------------------------------------------------------
// K3: scan within one chunk (32 steps), seeded by g_Tpre.
// grid = NCH * Pn = 2048 blocks, 64 threads; thread owns float4 of d.
// ---------------------------------------------------------------------------
__global__ void __launch_bounds__(64) k3_scan(float* __restrict__ out)
{
    __shared__ float cs[CH];
    const int p  = blockIdx.x & (Pn - 1);
    const int ch = blockIdx.x >> 5;
    const int lb = ch * CH;
    const int t  = threadIdx.x;     // 0..63 -> d4 group

    if (t < CH) cs[t] = g_cos[(size_t)(lb + t) * Pn + p];
    __syncthreads();

    float4 re = reinterpret_cast<const float4*>(g_Tpre)
                    [((size_t)ch * Pn + p) * (Dn / 4) + t];
    const float4* vp = reinterpret_cast<const float4*>(g_values)
                           + (size_t)lb * (Dn / 4) + t;
    float4* op = reinterpret_cast<float4*>(out)
                     + ((size_t)lb * Pn + p) * (Dn / 4) + t;

#pragma unroll
    for (int l = 0; l < CH; ++l) {
        const float  c = cs[l];
        const float4 v = vp[(size_t)l * (Dn / 4)];
        re.x = fmaf(c, v.x, re.x);
        re.y = fmaf(c, v.y, re.y);
        re.z = fmaf(c, v.z, re.z);
        re.w = fmaf(c, v.w, re.w);
        op[(size_t)l * (Pn * Dn / 4)] = re;
    }
}

// ---------------------------------------------------------------------------
extern "C" void kernel_launch(void* const* d_in, const int* in_sizes, int n_in,
                              void* d_out, int out_size)
{
    // Verify canonical contract (confirmed by R5 dump, dict order)
    if (n_in < 5 ||
        in_sizes[0] != BLn * Dn || in_sizes[1] != Dn * Pn ||
        in_sizes[2] != Pn       || in_sizes[3] != Dn * Dn ||
        in_sizes[4] != Dn) {
        fprintf(stderr, "[klaunch] BAIL: unexpected input sizes\n");
        return;
    }
    const float* x  = (const float*)d_in[0];
    const float* Wp = (const float*)d_in[1];
    const float* bp = (const float*)d_in[2];
    const float* Wv = (const float*)d_in[3];
    const float* bv = (const float*)d_in[4];

    float* out = (float*)d_out;
    const long long n = out_size;

    // Real-part layout: real(mem) [MEMR] | phases [PHN] | real(phasors) [PHN]
    if (n < MEMR) {
        fprintf(stderr, "[klaunch] BAIL: out_size=%lld < MEMR=%lld\n", n, MEMR);
        return;
    }
    const int has_aux = (n >= MEMR + 2 * PHN);
    float* out_phases     = has_aux ? (out + MEMR)       : nullptr;
    float* out_phasors_re = has_aux ? (out + MEMR + PHN) : nullptr;

    k1p_phase<<<BLn, 256>>>(x, Wp, bp, out_phases, out_phasors_re);
    k1v_values<<<BLn / 8, dim3(64, 4)>>>(x, Wv, bv);
    k2_chunktotals<<<NCH * 4, 256>>>();
    k2b_prefix<<<2 * Pn * 4, 64>>>();
    k3_scan<<<NCH * Pn, 64>>>(out);
}

// round 10
// speedup vs baseline: 1.3087x; 1.3087x over previous
#include <cuda_runtime.h>
#include <cstdio>
#include <math.h>

// Canonical dims (confirmed via R5 diagnostic dump)
#define BLn  2048      // B*L
#define Ln   1024
#define Dn   256
#define Pn   32
#define CH   32        // chunk length (in l)
#define NCH  (BLn/CH)  // 64 chunks
#define CPB  (Ln/CH)   // 32 chunks per batch

#define MEMR ((long long)BLn * Pn * Dn)   // 16,777,216 f32 (real(memory))
#define PHN  ((long long)BLn * Pn)        // 65,536

// Scratch (__device__ globals; no allocation)
__device__ float g_values[BLn * Dn];      // 2 MB
__device__ float g_cos[BLn * Pn];         // 256 KB
__device__ float g_T[NCH * Pn * Dn];      // 2 MB  chunk totals (real)
__device__ float g_Tpre[NCH * Pn * Dn];   // 2 MB  exclusive chunk prefixes

// ---------------------------------------------------------------------------
// K1p: phase = tanh(x@Wp + bp)*pi ; cos(phase)
// One block per row; 256 threads = 8 k-groups x 32 p; smem tree reduce.
// ---------------------------------------------------------------------------
__global__ void __launch_bounds__(256) k1p_phase(
    const float* __restrict__ x,
    const float* __restrict__ Wp,   // [D, P]
    const float* __restrict__ bp,   // [P]
    float* __restrict__ out_phases,      // may be null
    float* __restrict__ out_phasors_re)  // may be null
{
    __shared__ float xr[Dn];
    __shared__ float part[8][Pn];
    const int row = blockIdx.x;
    const int tid = threadIdx.x;

    xr[tid] = x[(size_t)row * Dn + tid];
    __syncthreads();

    const int p = tid & 31, g = tid >> 5;
    const int k0 = g * 32;
    float s = 0.0f;
#pragma unroll
    for (int k = 0; k < 32; ++k)
        s = fmaf(xr[k0 + k], Wp[(k0 + k) * Pn + p], s);
    part[g][p] = s;
    __syncthreads();

    if (tid < Pn) {
        float pacc = bp[tid];
#pragma unroll
        for (int gg = 0; gg < 8; ++gg) pacc += part[gg][tid];
        const float phase = tanhf(pacc) * 3.14159274101257324f;
        const float c = cosf(phase);
        const size_t idx = (size_t)row * Pn + tid;
        g_cos[idx] = c;
        if (out_phases)     out_phases[idx]     = phase;
        if (out_phasors_re) out_phasors_re[idx] = c;
    }
}

// ---------------------------------------------------------------------------
// K1v: values = x@Wv + bv
// 8 rows/block -> 256 blocks; block dim3(64,4); thread = 2 rows x 4 cols.
// ---------------------------------------------------------------------------
__global__ void __launch_bounds__(256) k1v_values(
    const float* __restrict__ x,
    const float* __restrict__ Wv,   // [D, D]
    const float* __restrict__ bv)   // [D]
{
    __shared__ float xs[8][Dn];     // 8 KB
    const int tx  = threadIdx.x;    // 0..63 -> float4 col group
    const int ty  = threadIdx.y;    // 0..3
    const int tid = ty * 64 + tx;
    const int row0 = blockIdx.x * 8;

    for (int i = tid; i < 8 * Dn; i += 256)
        xs[i >> 8][i & (Dn - 1)] = x[(size_t)row0 * Dn + i];
    __syncthreads();

    const float4 bvv = reinterpret_cast<const float4*>(bv)[tx];
    float4 a0 = bvv, a1 = bvv;

    const float4* Wv4 = reinterpret_cast<const float4*>(Wv);
#pragma unroll 8
    for (int k = 0; k < Dn; ++k) {
        const float4 w  = Wv4[k * 64 + tx];
        const float  x0 = xs[ty][k];
        const float  x1 = xs[ty + 4][k];
        a0.x = fmaf(x0, w.x, a0.x);
        a0.y = fmaf(x0, w.y, a0.y);
        a0.z = fmaf(x0, w.z, a0.z);
        a0.w = fmaf(x0, w.w, a0.w);
        a1.x = fmaf(x1, w.x, a1.x);
        a1.y = fmaf(x1, w.y, a1.y);
        a1.z = fmaf(x1, w.z, a1.z);
        a1.w = fmaf(x1, w.w, a1.w);
    }
    reinterpret_cast<float4*>(g_values)[(size_t)(row0 + ty) * 64 + tx]     = a0;
    reinterpret_cast<float4*>(g_values)[(size_t)(row0 + ty + 4) * 64 + tx] = a1;
}

// ---------------------------------------------------------------------------
// K2: chunk totals T[ch][p][d] = sum_{l in ch} cos[l][p] * value[l][d]
// (R8 version — proven at 60.2us total.)
// grid NCH=64 blocks, 256 threads (one d each), 32 p-accumulators per thread
// ---------------------------------------------------------------------------
__global__ void __launch_bounds__(256) k2_chunktotals()
{
    __shared__ float cs[CH][Pn];   // 4 KB
    const int ch  = blockIdx.x;
    const int d   = threadIdx.x;
    const int lb  = ch * CH;

    for (int i = threadIdx.x; i < CH * Pn; i += 256)
        cs[i >> 5][i & 31] = g_cos[(size_t)lb * Pn + i];
    __syncthreads();

    float acc[Pn];
#pragma unroll
    for (int p = 0; p < Pn; ++p) acc[p] = 0.0f;

#pragma unroll 2
    for (int l = 0; l < CH; ++l) {
        const float v = g_values[(size_t)(lb + l) * Dn + d];
#pragma unroll
        for (int q = 0; q < Pn / 4; ++q) {
            const float4 c4 = *reinterpret_cast<const float4*>(&cs[l][q * 4]);
            acc[q * 4 + 0] = fmaf(c4.x, v, acc[q * 4 + 0]);
            acc[q * 4 + 1] = fmaf(c4.y, v, acc[q * 4 + 1]);
            acc[q * 4 + 2] = fmaf(c4.z, v, acc[q * 4 + 2]);
            acc[q * 4 + 3] = fmaf(c4.w, v, acc[q * 4 + 3]);
        }
    }
#pragma unroll
    for (int p = 0; p < Pn; ++p)
        g_T[((size_t)ch * Pn + p) * Dn + d] = acc[p];
}

// ---------------------------------------------------------------------------
// K2b: exclusive prefix over the 32 chunks of each batch.
// grid = 2 batches * 32 p = 64 blocks, 64 threads (thread owns float4 of d).
// All 32 loads issued up front (high MLP), prefix in regs, 32 stores.
// (Measured 7.7us in R9; dead dq blocks removed.)
// ---------------------------------------------------------------------------
__global__ void __launch_bounds__(64) k2b_prefix()
{
    const int p     = blockIdx.x & 31;
    const int batch = blockIdx.x >> 5;
    const int ch0   = batch * CPB;
    const int t     = threadIdx.x;          // 0..63 float4 groups of d

    const float4* T4   = reinterpret_cast<const float4*>(g_T);
    float4*       Tp4  = reinterpret_cast<float4*>(g_Tpre);
    const size_t  base = ((size_t)ch0 * Pn + p) * (Dn / 4) + t;
    const size_t  str  = (size_t)Pn * (Dn / 4);

    float4 v[CPB];
#pragma unroll
    for (int c = 0; c < CPB; ++c)
        v[c] = T4[base + (size_t)c * str];

    float4 run = make_float4(0.f, 0.f, 0.f, 0.f);
#pragma unroll
    for (int c = 0; c < CPB; ++c) {
        const float4 cur = v[c];
        Tp4[base + (size_t)c * str] = run;
        run.x += cur.x;
        run.y += cur.y;
        run.z += cur.z;
        run.w += cur.w;
    }
}

// ---------------------------------------------------------------------------
// K3: scan within one chunk (32 steps), seeded by g_Tpre.
// grid = NCH * Pn = 2048 blocks, 64 threads; thread owns float4 of d.
// ---------------------------------------------------------------------------
__global__ void __launch_bounds__(64) k3_scan(float* __restrict__ out)
{
    __shared__ float cs[CH];
    const int p  = blockIdx.x & (Pn - 1);
    const int ch = blockIdx.x >> 5;
    const int lb = ch * CH;
    const int t  = threadIdx.x;     // 0..63 -> d4 group

    if (t < CH) cs[t] = g_cos[(size_t)(lb + t) * Pn + p];
    __syncthreads();

    float4 re = reinterpret_cast<const float4*>(g_Tpre)
                    [((size_t)ch * Pn + p) * (Dn / 4) + t];
    const float4* vp = reinterpret_cast<const float4*>(g_values)
                           + (size_t)lb * (Dn / 4) + t;
    float4* op = reinterpret_cast<float4*>(out)
                     + ((size_t)lb * Pn + p) * (Dn / 4) + t;

#pragma unroll
    for (int l = 0; l < CH; ++l) {
        const float  c = cs[l];
        const float4 v = vp[(size_t)l * (Dn / 4)];
        re.x = fmaf(c, v.x, re.x);
        re.y = fmaf(c, v.y, re.y);
        re.z = fmaf(c, v.z, re.z);
        re.w = fmaf(c, v.w, re.w);
        op[(size_t)l * (Pn * Dn / 4)] = re;
    }
}

// ---------------------------------------------------------------------------
extern "C" void kernel_launch(void* const* d_in, const int* in_sizes, int n_in,
                              void* d_out, int out_size)
{
    // Verify canonical contract (confirmed by R5 dump, dict order)
    if (n_in < 5 ||
        in_sizes[0] != BLn * Dn || in_sizes[1] != Dn * Pn ||
        in_sizes[2] != Pn       || in_sizes[3] != Dn * Dn ||
        in_sizes[4] != Dn) {
        fprintf(stderr, "[klaunch] BAIL: unexpected input sizes\n");
        return;
    }
    const float* x  = (const float*)d_in[0];
    const float* Wp = (const float*)d_in[1];
    const float* bp = (const float*)d_in[2];
    const float* Wv = (const float*)d_in[3];
    const float* bv = (const float*)d_in[4];

    float* out = (float*)d_out;
    const long long n = out_size;

    // Real-part layout: real(mem) [MEMR] | phases [PHN] | real(phasors) [PHN]
    if (n < MEMR) {
        fprintf(stderr, "[klaunch] BAIL: out_size=%lld < MEMR=%lld\n", n, MEMR);
        return;
    }
    const int has_aux = (n >= MEMR + 2 * PHN);
    float* out_phases     = has_aux ? (out + MEMR)       : nullptr;
    float* out_phasors_re = has_aux ? (out + MEMR + PHN) : nullptr;

    k1p_phase<<<BLn, 256>>>(x, Wp, bp, out_phases, out_phasors_re);
    k1v_values<<<BLn / 8, dim3(64, 4)>>>(x, Wv, bv);
    k2_chunktotals<<<NCH, 256>>>();
    k2b_prefix<<<2 * Pn, 64>>>();
    k3_scan<<<NCH * Pn, 64>>>(out);
}